// round 1
// baseline (speedup 1.0000x reference)
#include <cuda_runtime.h>
#include <math.h>

#define NB 2048
#define NC 50000
#define ND 128
#define SSCALE 20.0f
#define COS_M 0.99500416527802576f
#define SIN_M 0.09983341664682815f
#define EPSC 1e-7f

// scratch (static device globals — allocation-free per harness rules)
__device__ float g_invx[NB];
__device__ float g_invW[NC];
__device__ float g_rowloss[NB];

__device__ __forceinline__ float warpMax(float v) {
    #pragma unroll
    for (int o = 16; o; o >>= 1) v = fmaxf(v, __shfl_xor_sync(0xffffffffu, v, o));
    return v;
}
__device__ __forceinline__ float warpSum(float v) {
    #pragma unroll
    for (int o = 16; o; o >>= 1) v += __shfl_xor_sync(0xffffffffu, v, o);
    return v;
}

// ---------------------------------------------------------------------------
// K1: per-row 1/max(||row||, 1e-12). which=0 -> g_invx, which=1 -> g_invW
// ---------------------------------------------------------------------------
__global__ void invnorm_kernel(const float* __restrict__ src, int which)
{
    int row = blockIdx.x;
    float v = src[(size_t)row * ND + threadIdx.x];
    float ss = v * v;
    ss = warpSum(ss);
    __shared__ float sb[4];
    if ((threadIdx.x & 31) == 0) sb[threadIdx.x >> 5] = ss;
    __syncthreads();
    if (threadIdx.x == 0) {
        float t = sb[0] + sb[1] + sb[2] + sb[3];
        float inv = 1.0f / fmaxf(sqrtf(t), 1e-12f);
        if (which) g_invW[row] = inv;
        else       g_invx[row] = inv;
    }
}

// ---------------------------------------------------------------------------
// K2: wf = (x @ W^T) * invx * invW + b   -> written into d_out (scratch)
// 128x128 tile, K-chunk 16, 256 threads, 8x8 per thread.
// ---------------------------------------------------------------------------
#define BM 128
#define BN 128
#define TK 16

__global__ __launch_bounds__(256) void gemm_wf_kernel(
    const float* __restrict__ x, const float* __restrict__ W,
    const float* __restrict__ bias, float* __restrict__ out)
{
    __shared__ __align__(16) float As[TK][BM + 4];
    __shared__ __align__(16) float Bs[TK][BN + 4];

    const int row0 = blockIdx.y * BM;
    const int col0 = blockIdx.x * BN;
    const int tid  = threadIdx.x;
    const int tx = tid & 15, ty = tid >> 4;
    const int m0 = ty * 8, n0 = tx * 8;

    float acc[8][8];
    #pragma unroll
    for (int i = 0; i < 8; i++)
        #pragma unroll
        for (int j = 0; j < 8; j++) acc[i][j] = 0.0f;

    for (int k0 = 0; k0 < ND; k0 += TK) {
        #pragma unroll
        for (int it = 0; it < 2; it++) {
            int f  = tid + it * 256;          // 0..511 float4 slots
            int r  = f >> 2;                  // tile row 0..127
            int kq = (f & 3) << 2;            // k offset 0,4,8,12
            float4 va = *(const float4*)(x + (size_t)(row0 + r) * ND + k0 + kq);
            As[kq + 0][r] = va.x; As[kq + 1][r] = va.y;
            As[kq + 2][r] = va.z; As[kq + 3][r] = va.w;
            int gc = col0 + r;
            float4 vb = make_float4(0.f, 0.f, 0.f, 0.f);
            if (gc < NC) vb = *(const float4*)(W + (size_t)gc * ND + k0 + kq);
            Bs[kq + 0][r] = vb.x; Bs[kq + 1][r] = vb.y;
            Bs[kq + 2][r] = vb.z; Bs[kq + 3][r] = vb.w;
        }
        __syncthreads();
        #pragma unroll
        for (int kk = 0; kk < TK; kk++) {
            float4 a0 = *(const float4*)&As[kk][m0];
            float4 a1 = *(const float4*)&As[kk][m0 + 4];
            float4 b0 = *(const float4*)&Bs[kk][n0];
            float4 b1 = *(const float4*)&Bs[kk][n0 + 4];
            float a[8]  = {a0.x, a0.y, a0.z, a0.w, a1.x, a1.y, a1.z, a1.w};
            float bb[8] = {b0.x, b0.y, b0.z, b0.w, b1.x, b1.y, b1.z, b1.w};
            #pragma unroll
            for (int i = 0; i < 8; i++)
                #pragma unroll
                for (int j = 0; j < 8; j++)
                    acc[i][j] = fmaf(a[i], bb[j], acc[i][j]);
        }
        __syncthreads();
    }

    int gc0 = col0 + n0;
    if (gc0 < NC) {   // NC % 8 == 0, so the whole 8-col group is valid
        float iw[8], bv[8];
        #pragma unroll
        for (int j = 0; j < 8; j++) { iw[j] = g_invW[gc0 + j]; bv[j] = bias[gc0 + j]; }
        #pragma unroll
        for (int i = 0; i < 8; i++) {
            int gr = row0 + m0 + i;
            float ix = g_invx[gr];
            float o[8];
            #pragma unroll
            for (int j = 0; j < 8; j++) o[j] = fmaf(acc[i][j], ix * iw[j], bv[j]);
            float* p = out + (size_t)gr * NC + gc0;
            *(float4*)(p)     = make_float4(o[0], o[1], o[2], o[3]);
            *(float4*)(p + 4) = make_float4(o[4], o[5], o[6], o[7]);
        }
    }
}

// ---------------------------------------------------------------------------
// K3: per-row. Reads wf (scratch in d_out), writes prediction over it,
// computes per-row ArcFace CE loss term into g_rowloss.
// ---------------------------------------------------------------------------
__global__ __launch_bounds__(256) void softmax_loss_kernel(
    float* __restrict__ buf, const int* __restrict__ labels)
{
    const int row = blockIdx.x;
    const int tid = threadIdx.x;
    float* rowp = buf + (size_t)row * NC;
    const int lab = labels[row];

    __shared__ float s_cosm;
    __shared__ float sA[8], sB[8];

    // sweep 1: maxes (m1 over wf; mm over modified row for the loss softmax)
    float m1 = -1e30f, mm = -1e30f;
    for (int j = tid; j < NC; j += 256) {
        float v = rowp[j];
        float vm = v;
        if (j == lab) {
            float c  = fminf(fmaxf(v, -1.0f + EPSC), 1.0f - EPSC);
            float cm = c * COS_M - sqrtf(fmaxf(1.0f - c * c, 0.0f)) * SIN_M;
            s_cosm = cm;
            vm = cm;
        }
        m1 = fmaxf(m1, v);
        mm = fmaxf(mm, vm);
    }
    m1 = warpMax(m1); mm = warpMax(mm);
    if ((tid & 31) == 0) { sA[tid >> 5] = m1; sB[tid >> 5] = mm; }
    __syncthreads();
    if (tid == 0) {
        float a = sA[0], b = sB[0];
        #pragma unroll
        for (int i = 1; i < 8; i++) { a = fmaxf(a, sA[i]); b = fmaxf(b, sB[i]); }
        sA[0] = a; sB[0] = b;
    }
    __syncthreads();
    m1 = sA[0]; mm = sB[0];
    const float cosm = s_cosm;
    __syncthreads();

    // sweep 2: sums (rows live in L2 now)
    float s1 = 0.f, s2 = 0.f;
    for (int j = tid; j < NC; j += 256) {
        float v = rowp[j];
        s1 += __expf(v - m1);
        float vm = (j == lab) ? cosm : v;
        s2 += __expf(SSCALE * (vm - mm));
    }
    s1 = warpSum(s1); s2 = warpSum(s2);
    if ((tid & 31) == 0) { sA[tid >> 5] = s1; sB[tid >> 5] = s2; }
    __syncthreads();
    if (tid == 0) {
        float a = 0.f, b = 0.f;
        #pragma unroll
        for (int i = 0; i < 8; i++) { a += sA[i]; b += sB[i]; }
        sA[0] = a; sB[0] = b;
    }
    __syncthreads();
    s1 = sA[0]; s2 = sB[0];

    // sweep 3: overwrite wf with prediction
    const float inv1 = 1.0f / s1;
    for (int j = tid; j < NC; j += 256)
        rowp[j] = __expf(rowp[j] - m1) * inv1;

    if (tid == 0)
        g_rowloss[row] = SSCALE * mm + __logf(s2) - SSCALE * cosm;
}

// ---------------------------------------------------------------------------
// K4: deterministic loss reduction -> d_out[out_size-1]
// ---------------------------------------------------------------------------
__global__ void loss_final_kernel(float* __restrict__ out, long long idx)
{
    const int tid = threadIdx.x;
    float s = 0.f;
    for (int j = tid; j < NB; j += 256) s += g_rowloss[j];
    s = warpSum(s);
    __shared__ float sb[8];
    if ((tid & 31) == 0) sb[tid >> 5] = s;
    __syncthreads();
    if (tid == 0) {
        float t = 0.f;
        #pragma unroll
        for (int i = 0; i < 8; i++) t += sb[i];
        out[idx] = t / (float)NB;
    }
}

// ---------------------------------------------------------------------------
extern "C" void kernel_launch(void* const* d_in, const int* in_sizes, int n_in,
                              void* d_out, int out_size)
{
    const float* x      = (const float*)d_in[0];  // [2048,128]
    const float* W      = (const float*)d_in[1];  // [50000,128]
    const float* b      = (const float*)d_in[2];  // [50000]
    const int*   labels = (const int*)  d_in[3];  // [2048]
    float* out = (float*)d_out;                   // [2048*50000 prediction] + [loss]

    invnorm_kernel<<<NB, ND>>>(x, 0);
    invnorm_kernel<<<NC, ND>>>(W, 1);

    dim3 grid((NC + BN - 1) / BN, NB / BM);
    gemm_wf_kernel<<<grid, 256>>>(x, W, b, out);

    softmax_loss_kernel<<<NB, 256>>>(out, labels);

    loss_final_kernel<<<1, 256>>>(out, (long long)out_size - 1);
}

// round 3
// speedup vs baseline: 1.1454x; 1.1454x over previous
#include <cuda_runtime.h>
#include <math.h>
#include <stdint.h>

#define NB 2048
#define NC 50000
#define ND 128
#define SSCALE 20.0f
#define COS_M 0.99500416527802576f
#define SIN_M 0.09983341664682815f
#define EPSC 1e-7f

__device__ float g_invx[NB];
__device__ float g_invW[NC];
__device__ float g_rowloss[NB];

__device__ __forceinline__ float warpMax(float v) {
    #pragma unroll
    for (int o = 16; o; o >>= 1) v = fmaxf(v, __shfl_xor_sync(0xffffffffu, v, o));
    return v;
}
__device__ __forceinline__ float warpSum(float v) {
    #pragma unroll
    for (int o = 16; o; o >>= 1) v += __shfl_xor_sync(0xffffffffu, v, o);
    return v;
}
__device__ __forceinline__ uint32_t f2tf32(float f) {
    uint32_t r;
    asm("cvt.rna.tf32.f32 %0, %1;\n" : "=r"(r) : "f"(f));
    return r;
}

// ---------------------------------------------------------------------------
// K1: per-row 1/max(||row||, 1e-12)
// ---------------------------------------------------------------------------
__global__ void invnorm_kernel(const float* __restrict__ src, int which)
{
    int row = blockIdx.x;
    float v = src[(size_t)row * ND + threadIdx.x];
    float ss = warpSum(v * v);
    __shared__ float sb[4];
    if ((threadIdx.x & 31) == 0) sb[threadIdx.x >> 5] = ss;
    __syncthreads();
    if (threadIdx.x == 0) {
        float t = sb[0] + sb[1] + sb[2] + sb[3];
        float inv = 1.0f / fmaxf(sqrtf(t), 1e-12f);
        if (which) g_invW[row] = inv;
        else       g_invx[row] = inv;
    }
}

// ---------------------------------------------------------------------------
// K2: tf32 mma.sync GEMM.  wf = (x @ W^T)*invx*invW + b  -> d_out scratch
// 128x128 block tile, K chunk 32, 8 warps (2x4), warp tile 64x32.
// ---------------------------------------------------------------------------
#define BM 128
#define BN 128
#define TK 32
#define PAD 4
#define LDW (TK + PAD)   // 36 floats per smem row

__global__ __launch_bounds__(256) void gemm_wf_kernel(
    const float* __restrict__ x, const float* __restrict__ W,
    const float* __restrict__ bias, float* __restrict__ out)
{
    __shared__ __align__(16) float As[BM][LDW];
    __shared__ __align__(16) float Bs[BN][LDW];

    const int row0 = blockIdx.y * BM;
    const int col0 = blockIdx.x * BN;
    const int tid  = threadIdx.x;
    const int warp = tid >> 5;
    const int lane = tid & 31;
    const int g    = lane >> 2;    // groupID 0..7
    const int tig  = lane & 3;     // thread-in-group 0..3
    const int wm   = warp >> 2;    // 0..1  -> 64-row slab
    const int wn   = warp & 3;     // 0..3  -> 32-col slab
    const int m_base = wm * 64;
    const int n_base = wn * 32;

    float acc[4][4][4];
    #pragma unroll
    for (int mi = 0; mi < 4; mi++)
        #pragma unroll
        for (int ni = 0; ni < 4; ni++)
            #pragma unroll
            for (int r = 0; r < 4; r++) acc[mi][ni][r] = 0.0f;

    const int lr  = tid >> 3;       // 0..31 row within 128 (x4 iters)
    const int lc4 = tid & 7;        // float4 index 0..7 within 32-K chunk

    for (int k0 = 0; k0 < ND; k0 += TK) {
        #pragma unroll
        for (int it = 0; it < 4; it++) {
            int r = lr + it * 32;
            float4 va = *(const float4*)(x + (size_t)(row0 + r) * ND + k0 + lc4 * 4);
            *(float4*)&As[r][lc4 * 4] = va;
            int gc = col0 + r;
            float4 vb = make_float4(0.f, 0.f, 0.f, 0.f);
            if (gc < NC) vb = *(const float4*)(W + (size_t)gc * ND + k0 + lc4 * 4);
            *(float4*)&Bs[r][lc4 * 4] = vb;
        }
        __syncthreads();

        #pragma unroll
        for (int ks = 0; ks < TK / 8; ks++) {
            const int kk = ks * 8;
            uint32_t a[4][4];
            #pragma unroll
            for (int mi = 0; mi < 4; mi++) {
                const int mr = m_base + mi * 16;
                a[mi][0] = f2tf32(As[mr + g    ][kk + tig    ]);
                a[mi][1] = f2tf32(As[mr + g + 8][kk + tig    ]);
                a[mi][2] = f2tf32(As[mr + g    ][kk + tig + 4]);
                a[mi][3] = f2tf32(As[mr + g + 8][kk + tig + 4]);
            }
            uint32_t bfr[4][2];
            #pragma unroll
            for (int ni = 0; ni < 4; ni++) {
                const int nr = n_base + ni * 8;
                bfr[ni][0] = f2tf32(Bs[nr + g][kk + tig    ]);
                bfr[ni][1] = f2tf32(Bs[nr + g][kk + tig + 4]);
            }
            #pragma unroll
            for (int mi = 0; mi < 4; mi++)
                #pragma unroll
                for (int ni = 0; ni < 4; ni++) {
                    asm volatile(
                        "mma.sync.aligned.m16n8k8.row.col.f32.tf32.tf32.f32 "
                        "{%0,%1,%2,%3}, {%4,%5,%6,%7}, {%8,%9}, {%0,%1,%2,%3};\n"
                        : "+f"(acc[mi][ni][0]), "+f"(acc[mi][ni][1]),
                          "+f"(acc[mi][ni][2]), "+f"(acc[mi][ni][3])
                        : "r"(a[mi][0]), "r"(a[mi][1]), "r"(a[mi][2]), "r"(a[mi][3]),
                          "r"(bfr[ni][0]), "r"(bfr[ni][1]));
                }
        }
        __syncthreads();
    }

    // epilogue: wf = acc * invx * invW + bias
    #pragma unroll
    for (int ni = 0; ni < 4; ni++) {
        const int c = col0 + n_base + ni * 8 + 2 * tig;   // even col
        if (c >= NC) continue;
        const float iw0 = g_invW[c],     iw1 = g_invW[c + 1];
        const float bv0 = bias[c],       bv1 = bias[c + 1];
        #pragma unroll
        for (int mi = 0; mi < 4; mi++) {
            const int r0 = row0 + m_base + mi * 16 + g;
            const int r1 = r0 + 8;
            const float ix0 = g_invx[r0], ix1 = g_invx[r1];
            float2 o0 = make_float2(fmaf(acc[mi][ni][0], ix0 * iw0, bv0),
                                    fmaf(acc[mi][ni][1], ix0 * iw1, bv1));
            float2 o1 = make_float2(fmaf(acc[mi][ni][2], ix1 * iw0, bv0),
                                    fmaf(acc[mi][ni][3], ix1 * iw1, bv1));
            *(float2*)(out + (size_t)r0 * NC + c) = o0;
            *(float2*)(out + (size_t)r1 * NC + c) = o1;
        }
    }
}

// ---------------------------------------------------------------------------
// K3: persistent softmax + loss. 512 blocks, 4 rows each -> active row
// footprint 100MB fits L2, so sweeps 2-3 hit L2.
// ---------------------------------------------------------------------------
#define SM_BLOCKS 512

__global__ __launch_bounds__(256) void softmax_loss_kernel(
    float* __restrict__ buf, const int* __restrict__ labels)
{
    const int tid = threadIdx.x;
    __shared__ float s_cosm;
    __shared__ float sA[8], sB[8];

    for (int row = blockIdx.x; row < NB; row += SM_BLOCKS) {
        float* rowp = buf + (size_t)row * NC;
        const int lab = labels[row];

        // sweep 1: maxes
        float m1 = -1e30f, mm = -1e30f;
        for (int j = tid; j < NC; j += 256) {
            float v = rowp[j];
            float vm = v;
            if (j == lab) {
                float c  = fminf(fmaxf(v, -1.0f + EPSC), 1.0f - EPSC);
                float cm = c * COS_M - sqrtf(fmaxf(1.0f - c * c, 0.0f)) * SIN_M;
                s_cosm = cm;
                vm = cm;
            }
            m1 = fmaxf(m1, v);
            mm = fmaxf(mm, vm);
        }
        m1 = warpMax(m1); mm = warpMax(mm);
        if ((tid & 31) == 0) { sA[tid >> 5] = m1; sB[tid >> 5] = mm; }
        __syncthreads();
        if (tid == 0) {
            float a = sA[0], b = sB[0];
            #pragma unroll
            for (int i = 1; i < 8; i++) { a = fmaxf(a, sA[i]); b = fmaxf(b, sB[i]); }
            sA[0] = a; sB[0] = b;
        }
        __syncthreads();
        m1 = sA[0]; mm = sB[0];
        const float cosm = s_cosm;
        __syncthreads();

        // sweep 2: sums (L2-resident)
        float s1 = 0.f, s2 = 0.f;
        for (int j = tid; j < NC; j += 256) {
            float v = rowp[j];
            s1 += __expf(v - m1);
            float vm = (j == lab) ? cosm : v;
            s2 += __expf(SSCALE * (vm - mm));
        }
        s1 = warpSum(s1); s2 = warpSum(s2);
        if ((tid & 31) == 0) { sA[tid >> 5] = s1; sB[tid >> 5] = s2; }
        __syncthreads();
        if (tid == 0) {
            float a = 0.f, b = 0.f;
            #pragma unroll
            for (int i = 0; i < 8; i++) { a += sA[i]; b += sB[i]; }
            sA[0] = a; sB[0] = b;
        }
        __syncthreads();
        s1 = sA[0]; s2 = sB[0];
        __syncthreads();

        // sweep 3: prediction overwrite (L2-resident read, write-through)
        const float inv1 = 1.0f / s1;
        for (int j = tid; j < NC; j += 256)
            rowp[j] = __expf(rowp[j] - m1) * inv1;

        if (tid == 0)
            g_rowloss[row] = SSCALE * mm + __logf(s2) - SSCALE * cosm;
        __syncthreads();
    }
}

// ---------------------------------------------------------------------------
// K4: deterministic loss reduction
// ---------------------------------------------------------------------------
__global__ void loss_final_kernel(float* __restrict__ out, long long idx)
{
    const int tid = threadIdx.x;
    float s = 0.f;
    for (int j = tid; j < NB; j += 256) s += g_rowloss[j];
    s = warpSum(s);
    __shared__ float sb[8];
    if ((tid & 31) == 0) sb[tid >> 5] = s;
    __syncthreads();
    if (tid == 0) {
        float t = 0.f;
        #pragma unroll
        for (int i = 0; i < 8; i++) t += sb[i];
        out[idx] = t / (float)NB;
    }
}

// ---------------------------------------------------------------------------
extern "C" void kernel_launch(void* const* d_in, const int* in_sizes, int n_in,
                              void* d_out, int out_size)
{
    const float* x      = (const float*)d_in[0];
    const float* W      = (const float*)d_in[1];
    const float* b      = (const float*)d_in[2];
    const int*   labels = (const int*)  d_in[3];
    float* out = (float*)d_out;

    invnorm_kernel<<<NB, ND>>>(x, 0);
    invnorm_kernel<<<NC, ND>>>(W, 1);

    dim3 grid((NC + BN - 1) / BN, NB / BM);
    gemm_wf_kernel<<<grid, 256>>>(x, W, b, out);

    softmax_loss_kernel<<<SM_BLOCKS, 256>>>(out, labels);

    loss_final_kernel<<<1, 256>>>(out, (long long)out_size - 1);
}